// round 6
// baseline (speedup 1.0000x reference)
#include <cuda_runtime.h>
#include <cuda_bf16.h>
#include <math.h>

#define HH 1024
#define NN 64
#define LL 1024
#define NG 8          // states per thread
#define LT 32         // number of l-chunk threads
#define CHUNK (LL/LT) // 32 l-values per thread
#define THREADS (LT*NG)
#define NP (NG/2)     // packed f32x2 pairs per thread
#define TSTRIDE 264   // padded per-t stride (floats) in partial buffer

typedef unsigned long long u64;

__device__ __forceinline__ u64 pack2(float lo, float hi) {
    u64 r; asm("mov.b64 %0, {%1, %2};" : "=l"(r) : "f"(lo), "f"(hi)); return r;
}
__device__ __forceinline__ void unpack2(u64 v, float& lo, float& hi) {
    asm("mov.b64 {%0, %1}, %2;" : "=f"(lo), "=f"(hi) : "l"(v));
}
__device__ __forceinline__ u64 mul2(u64 a, u64 b) {
    u64 r; asm("mul.rn.f32x2 %0, %1, %2;" : "=l"(r) : "l"(a), "l"(b)); return r;
}
__device__ __forceinline__ u64 fma2(u64 a, u64 b, u64 c) {
    u64 r; asm("fma.rn.f32x2 %0, %1, %2, %3;" : "=l"(r) : "l"(a), "l"(b), "l"(c)); return r;
}
__device__ __forceinline__ u64 add2(u64 a, u64 b) {
    u64 r; asm("add.rn.f32x2 %0, %1, %2;" : "=l"(r) : "l"(a), "l"(b)); return r;
}

__global__ __launch_bounds__(THREADS)
void ssk_diag_kernel(const float* __restrict__ log_dt,
                     const float* __restrict__ Lre,
                     const float* __restrict__ Lim,
                     const float* __restrict__ Bm,
                     const float* __restrict__ Cre,
                     const float* __restrict__ Cim,
                     const float* __restrict__ Dm,
                     float* __restrict__ out) {
    const int h = blockIdx.x;
    __shared__ float s_wre[NN], s_wim[NN];       // w = exp(dtA)
    __shared__ float s_cre[NN], s_cim[NN];       // 2*C*B_bar
    __shared__ float s_a[NN],   s_bn[NN];        // 2*Re(w), -|w|^2
    __shared__ float s_pre[5][NN], s_pim[5][NN]; // w^{32*2^k}, k=0..4
    __shared__ float s_part[31 * TSTRIDE + 31 * 8 + 8]; // partials, padded

    const int tid = threadIdx.x;

    // ---- setup: per-state parameters (64 threads) ----
    if (tid < NN) {
        const int idx = h * NN + tid;
        float dt  = expf(log_dt[h]);
        float lre = Lre[idx];
        float lim = Lim[idx];
        float are = dt * lre;
        float aim = dt * lim;
        float er  = expf(are);
        float s, c;
        sincosf(aim, &s, &c);            // sin first, cos second
        float wre = er * c;
        float wim = er * s;
        // expm1(dtA): Re = expm1(are)*cos(aim) - 2*sin^2(aim/2), Im = e^are*sin(aim)
        float em   = expm1f(are);
        float sh   = sinf(0.5f * aim);
        float emre = fmaf(em, c, -2.0f * sh * sh);
        float emim = er * s;
        // B_bar = expm1(dtA)/Lambda * B   (complex divide by Lambda)
        float inv  = 1.0f / fmaf(lre, lre, lim * lim);
        float bre  = (emre * lre + emim * lim) * inv;
        float bim  = (emim * lre - emre * lim) * inv;
        float b    = Bm[idx];
        bre *= b;  bim *= b;
        // CB = C * B_bar, fold in the factor 2 from 2*Re(K)
        float cr = Cre[idx], ci = Cim[idx];
        float cbre = 2.0f * (cr * bre - ci * bim);
        float cbim = 2.0f * (cr * bim + ci * bre);
        s_wre[tid] = wre;  s_wim[tid] = wim;
        s_cre[tid] = cbre; s_cim[tid] = cbim;
        s_a[tid]   = 2.0f * wre;
        s_bn[tid]  = -fmaf(wre, wre, wim * wim);
        // power ladder: 5 squarings to w^32, then store w^{32*2^k}, k=0..4
        float pr = wre, pi = wim;
        #pragma unroll
        for (int k = 0; k < 5; k++) {
            float nr = fmaf(pr, pr, -pi * pi);
            float ni = 2.0f * pr * pi;
            pr = nr; pi = ni;
        }
        #pragma unroll
        for (int k = 0; k < 5; k++) {
            s_pre[k][tid] = pr;
            s_pim[k][tid] = pi;
            float nr = fmaf(pr, pr, -pi * pi);
            float ni = 2.0f * pr * pi;
            pr = nr; pi = ni;
        }
    }
    __syncthreads();

    // ---- main: packed second-order real recurrence, partials to smem ----
    const int g  = tid & (NG - 1);   // state group
    const int t  = tid >> 3;         // l-chunk index (0..31)

    float x0[NG], x1[NG], av[NG], bv[NG];
    #pragma unroll
    for (int j = 0; j < NG; j++) {
        const int n = g * NG + j;
        const float wre = s_wre[n], wim = s_wim[n];
        const float cbre = s_cre[n], cbim = s_cim[n];
        av[j] = s_a[n];
        bv[j] = s_bn[n];
        // z = w^{l0} via binary ladder over set bits of t
        float zr = 1.0f, zi = 0.0f;
        #pragma unroll
        for (int k = 0; k < 5; k++) {
            if (t & (1 << k)) {
                float pr = s_pre[k][n], pi = s_pim[k][n];
                float nr = fmaf(zr, pr, -zi * pi);
                float ni = fmaf(zr, pi,  zi * pr);
                zr = nr; zi = ni;
            }
        }
        x0[j] = fmaf(cbre, zr, -cbim * zi);          // Re(cb * w^l0)
        float z1r = fmaf(zr, wre, -zi * wim);
        float z1i = fmaf(zr, wim,  zi * wre);
        x1[j] = fmaf(cbre, z1r, -cbim * z1i);        // Re(cb * w^(l0+1))
    }

    u64 P[NP], Q[NP], A2[NP], BN[NP];
    #pragma unroll
    for (int k = 0; k < NP; k++) {
        P[k]  = pack2(x0[2*k], x0[2*k+1]);
        Q[k]  = pack2(x1[2*k], x1[2*k+1]);
        A2[k] = pack2(av[2*k], av[2*k+1]);
        BN[k] = pack2(bv[2*k], bv[2*k+1]);
    }

    float* pbase = &s_part[t * TSTRIDE + g];
    #pragma unroll
    for (int i = 0; i < CHUNK; i++) {
        // partial sum over this thread's 8 states at l = t*32 + i
        u64 s01 = add2(P[0], P[1]);
        u64 s23 = add2(P[2], P[3]);
        u64 sp  = add2(s01, s23);
        float lo, hi;
        unpack2(sp, lo, hi);
        pbase[i * 8] = lo + hi;   // banks (8t+8i+g)&31: conflict-free
        // advance: x_{l+2} = a*x_{l+1} + bn*x_l
        #pragma unroll
        for (int k = 0; k < NP; k++) {
            u64 tt = mul2(BN[k], P[k]);
            u64 r2 = fma2(A2[k], Q[k], tt);
            P[k] = Q[k];
            Q[k] = r2;
        }
    }
    __syncthreads();

    // ---- epilogue: reduce 8 partials per l, write gmem directly ----
    const float Dh = Dm[h];
    float* outh = out + (size_t)h * LL;
    #pragma unroll
    for (int k = 0; k < 4; k++) {
        const int l  = k * 256 + tid;
        const int tt = l >> 5;
        const int ii = l & 31;
        const float* src = &s_part[tt * TSTRIDE + ii * 8];
        // 8 conflict-free LDS (bank = (8*lane + g) & 31 within a warp)
        float v0 = src[0] + src[1];
        float v1 = src[2] + src[3];
        float v2 = src[4] + src[5];
        float v3 = src[6] + src[7];
        float v  = (v0 + v1) + (v2 + v3);
        if (l == 0) v += Dh;
        outh[l] = v;
    }
}

extern "C" void kernel_launch(void* const* d_in, const int* in_sizes, int n_in,
                              void* d_out, int out_size) {
    const float* log_dt = (const float*)d_in[0];
    const float* Lre    = (const float*)d_in[1];
    const float* Lim    = (const float*)d_in[2];
    const float* Bm     = (const float*)d_in[3];
    const float* Cre    = (const float*)d_in[4];
    const float* Cim    = (const float*)d_in[5];
    const float* Dm     = (const float*)d_in[6];
    float* out = (float*)d_out;
    ssk_diag_kernel<<<HH, THREADS>>>(log_dt, Lre, Lim, Bm, Cre, Cim, Dm, out);
}

// round 7
// speedup vs baseline: 1.5009x; 1.5009x over previous
#include <cuda_runtime.h>
#include <cuda_bf16.h>
#include <math.h>

#define HH 1024
#define NN 64
#define LL 1024
#define NG 8            // states per thread
#define LT 16           // l-chunks
#define CHUNK (LL/LT)   // 64 l per thread
#define THREADS (LT*NG) // 128
#define NP (NG/2)
#define ROW 65          // padded chunk row stride (floats)
#define HALF_OFF (LT*ROW) // 1040 floats between half0/half1 partials

typedef unsigned long long u64;

__device__ __forceinline__ u64 pack2(float lo, float hi) {
    u64 r; asm("mov.b64 %0, {%1, %2};" : "=l"(r) : "f"(lo), "f"(hi)); return r;
}
__device__ __forceinline__ void unpack2(u64 v, float& lo, float& hi) {
    asm("mov.b64 {%0, %1}, %2;" : "=f"(lo), "=f"(hi) : "l"(v));
}
__device__ __forceinline__ u64 mul2(u64 a, u64 b) {
    u64 r; asm("mul.rn.f32x2 %0, %1, %2;" : "=l"(r) : "l"(a), "l"(b)); return r;
}
__device__ __forceinline__ u64 fma2(u64 a, u64 b, u64 c) {
    u64 r; asm("fma.rn.f32x2 %0, %1, %2, %3;" : "=l"(r) : "l"(a), "l"(b), "l"(c)); return r;
}
__device__ __forceinline__ u64 add2(u64 a, u64 b) {
    u64 r; asm("add.rn.f32x2 %0, %1, %2;" : "=l"(r) : "l"(a), "l"(b)); return r;
}

__global__ __launch_bounds__(THREADS)
void ssk_diag_kernel(const float* __restrict__ log_dt,
                     const float* __restrict__ Lre,
                     const float* __restrict__ Lim,
                     const float* __restrict__ Bm,
                     const float* __restrict__ Cre,
                     const float* __restrict__ Cim,
                     const float* __restrict__ Dm,
                     float* __restrict__ out) {
    const int h = blockIdx.x;
    __shared__ float s_wre[NN], s_wim[NN];       // w = exp(dtA)
    __shared__ float s_cre[NN], s_cim[NN];       // 2*C*B_bar
    __shared__ float s_pre[4][NN], s_pim[4][NN]; // w^{64*2^k}, k=0..3
    __shared__ float s_part[2 * HALF_OFF];       // two half-sums per l, padded

    const int tid = threadIdx.x;

    // ---- setup: per-state parameters (64 threads) ----
    if (tid < NN) {
        const int idx = h * NN + tid;
        float dt  = expf(log_dt[h]);
        float lre = Lre[idx];
        float lim = Lim[idx];
        float are = dt * lre;
        float aim = dt * lim;
        float er  = expf(are);
        float s, c;
        sincosf(aim, &s, &c);            // sin first, cos second
        float wre = er * c;
        float wim = er * s;
        // expm1(dtA): Re = expm1(are)*cos(aim) - 2*sin^2(aim/2), Im = e^are*sin(aim)
        float em   = expm1f(are);
        float sh   = sinf(0.5f * aim);
        float emre = fmaf(em, c, -2.0f * sh * sh);
        float emim = er * s;
        // B_bar = expm1(dtA)/Lambda * B
        float inv  = 1.0f / fmaf(lre, lre, lim * lim);
        float bre  = (emre * lre + emim * lim) * inv;
        float bim  = (emim * lre - emre * lim) * inv;
        float b    = Bm[idx];
        bre *= b;  bim *= b;
        // CB = C * B_bar, fold factor 2
        float cr = Cre[idx], ci = Cim[idx];
        float cbre = 2.0f * (cr * bre - ci * bim);
        float cbim = 2.0f * (cr * bim + ci * bre);
        s_wre[tid] = wre;  s_wim[tid] = wim;
        s_cre[tid] = cbre; s_cim[tid] = cbim;
        // ladder: 6 squarings to w^64, then store w^{64*2^k}, k=0..3
        float pr = wre, pi = wim;
        #pragma unroll
        for (int k = 0; k < 6; k++) {
            float nr = fmaf(pr, pr, -pi * pi);
            float ni = 2.0f * pr * pi;
            pr = nr; pi = ni;
        }
        #pragma unroll
        for (int k = 0; k < 4; k++) {
            s_pre[k][tid] = pr;
            s_pim[k][tid] = pi;
            float nr = fmaf(pr, pr, -pi * pi);
            float ni = 2.0f * pr * pi;
            pr = nr; pi = ni;
        }
    }
    __syncthreads();

    // ---- main: packed second-order real recurrence ----
    const int g  = tid & (NG - 1);   // state group (lane & 7)
    const int t  = tid >> 3;         // l-chunk (0..15)

    float x0[NG], x1[NG], av[NG], bv[NG];
    #pragma unroll
    for (int j = 0; j < NG; j++) {
        const int n = g * NG + j;
        const float wre = s_wre[n], wim = s_wim[n];
        const float cbre = s_cre[n], cbim = s_cim[n];
        av[j] = 2.0f * wre;
        bv[j] = -fmaf(wre, wre, wim * wim);
        // z = w^{64t} via binary ladder over 4 bits of t
        float zr = 1.0f, zi = 0.0f;
        #pragma unroll
        for (int k = 0; k < 4; k++) {
            if (t & (1 << k)) {
                float pr = s_pre[k][n], pi = s_pim[k][n];
                float nr = fmaf(zr, pr, -zi * pi);
                float ni = fmaf(zr, pi,  zi * pr);
                zr = nr; zi = ni;
            }
        }
        x0[j] = fmaf(cbre, zr, -cbim * zi);          // Re(cb * w^l0)
        float z1r = fmaf(zr, wre, -zi * wim);
        float z1i = fmaf(zr, wim,  zi * wre);
        x1[j] = fmaf(cbre, z1r, -cbim * z1i);        // Re(cb * w^(l0+1))
    }

    u64 P[NP], Q[NP], A2[NP], BN[NP];
    #pragma unroll
    for (int k = 0; k < NP; k++) {
        P[k]  = pack2(x0[2*k], x0[2*k+1]);
        Q[k]  = pack2(x1[2*k], x1[2*k+1]);
        A2[k] = pack2(av[2*k], av[2*k+1]);
        BN[k] = pack2(bv[2*k], bv[2*k+1]);
    }

    // storing lanes: g == 0 (half 0) and g == 4 (half 1)
    const bool storer = (g & 3) == 0;
    float* pbase = &s_part[(g >> 2) * HALF_OFF + t * ROW];

    #pragma unroll 16
    for (int i = 0; i < CHUNK; i++) {
        // partial sum over this thread's 8 states
        u64 s01 = add2(P[0], P[1]);
        u64 s23 = add2(P[2], P[3]);
        u64 sp  = add2(s01, s23);
        float lo, hi;
        unpack2(sp, lo, hi);
        float part = lo + hi;
        // reduce 8 groups -> 2 half-sums (lanes g and g^1, g^2)
        part += __shfl_xor_sync(0xffffffffu, part, 1);
        part += __shfl_xor_sync(0xffffffffu, part, 2);
        if (storer) pbase[i] = part;   // banks (t+i)&31 / +16: conflict-free
        // advance: x_{l+2} = a*x_{l+1} + bn*x_l
        #pragma unroll
        for (int k = 0; k < NP; k++) {
            u64 tt = mul2(BN[k], P[k]);
            u64 r2 = fma2(A2[k], Q[k], tt);
            P[k] = Q[k];
            Q[k] = r2;
        }
    }
    __syncthreads();

    // ---- epilogue: add the two halves, write gmem coalesced ----
    const float Dh = Dm[h];
    float* outh = out + (size_t)h * LL;
    #pragma unroll
    for (int k = 0; k < 8; k++) {
        const int l  = k * THREADS + tid;
        const int tt = l >> 6;            // chunk
        const int ii = l & 63;            // offset in chunk
        const int a  = tt * ROW + ii;
        float v = s_part[a] + s_part[a + HALF_OFF];
        if (l == 0) v += Dh;
        outh[l] = v;
    }
}

extern "C" void kernel_launch(void* const* d_in, const int* in_sizes, int n_in,
                              void* d_out, int out_size) {
    const float* log_dt = (const float*)d_in[0];
    const float* Lre    = (const float*)d_in[1];
    const float* Lim    = (const float*)d_in[2];
    const float* Bm     = (const float*)d_in[3];
    const float* Cre    = (const float*)d_in[4];
    const float* Cim    = (const float*)d_in[5];
    const float* Dm     = (const float*)d_in[6];
    float* out = (float*)d_out;
    ssk_diag_kernel<<<HH, THREADS>>>(log_dt, Lre, Lim, Bm, Cre, Cim, Dm, out);
}

// round 8
// speedup vs baseline: 1.6794x; 1.1189x over previous
#include <cuda_runtime.h>
#include <cuda_bf16.h>
#include <math.h>

#define HH 1024
#define NN 64
#define LL 1024
#define NG 8            // states per thread
#define LT 16           // l-chunks
#define CHUNK (LL/LT)   // 64 l per thread
#define THREADS (LT*NG) // 128
#define NP (NG/2)
#define TROW 68         // per-chunk row stride (floats), 16B-aligned
#define QSTRIDE (LT*TROW + 8)  // 1096: quarter stride, bank offset 8

typedef unsigned long long u64;

__device__ __forceinline__ u64 pack2(float lo, float hi) {
    u64 r; asm("mov.b64 %0, {%1, %2};" : "=l"(r) : "f"(lo), "f"(hi)); return r;
}
__device__ __forceinline__ void unpack2(u64 v, float& lo, float& hi) {
    asm("mov.b64 {%0, %1}, %2;" : "=f"(lo), "=f"(hi) : "l"(v));
}
__device__ __forceinline__ u64 mul2(u64 a, u64 b) {
    u64 r; asm("mul.rn.f32x2 %0, %1, %2;" : "=l"(r) : "l"(a), "l"(b)); return r;
}
__device__ __forceinline__ u64 fma2(u64 a, u64 b, u64 c) {
    u64 r; asm("fma.rn.f32x2 %0, %1, %2, %3;" : "=l"(r) : "l"(a), "l"(b), "l"(c)); return r;
}
__device__ __forceinline__ u64 add2(u64 a, u64 b) {
    u64 r; asm("add.rn.f32x2 %0, %1, %2;" : "=l"(r) : "l"(a), "l"(b)); return r;
}

__global__ __launch_bounds__(THREADS)
void ssk_diag_kernel(const float* __restrict__ log_dt,
                     const float* __restrict__ Lre,
                     const float* __restrict__ Lim,
                     const float* __restrict__ Bm,
                     const float* __restrict__ Cre,
                     const float* __restrict__ Cim,
                     const float* __restrict__ Dm,
                     float* __restrict__ out) {
    const int h = blockIdx.x;
    __shared__ float s_wre[NN], s_wim[NN];       // w = exp(dtA)
    __shared__ float s_cre[NN], s_cim[NN];       // 2*C*B_bar
    __shared__ float s_pre[4][NN], s_pim[4][NN]; // w^{64*2^k}, k=0..3
    __shared__ float s_part[4 * QSTRIDE];        // 4 quarter-sums per l

    const int tid = threadIdx.x;

    // ---- setup: per-state parameters (64 threads) ----
    if (tid < NN) {
        const int idx = h * NN + tid;
        float dt  = expf(log_dt[h]);
        float lre = Lre[idx];
        float lim = Lim[idx];
        float are = dt * lre;
        float aim = dt * lim;
        float er  = expf(are);
        float s, c;
        sincosf(aim, &s, &c);            // sin first, cos second
        float wre = er * c;
        float wim = er * s;
        // expm1(dtA): Re = expm1(are)*cos(aim) - 2*sin^2(aim/2), Im = e^are*sin(aim)
        float em   = expm1f(are);
        float sh   = sinf(0.5f * aim);
        float emre = fmaf(em, c, -2.0f * sh * sh);
        float emim = er * s;
        // B_bar = expm1(dtA)/Lambda * B
        float inv  = 1.0f / fmaf(lre, lre, lim * lim);
        float bre  = (emre * lre + emim * lim) * inv;
        float bim  = (emim * lre - emre * lim) * inv;
        float b    = Bm[idx];
        bre *= b;  bim *= b;
        // CB = C * B_bar, fold factor 2
        float cr = Cre[idx], ci = Cim[idx];
        float cbre = 2.0f * (cr * bre - ci * bim);
        float cbim = 2.0f * (cr * bim + ci * bre);
        s_wre[tid] = wre;  s_wim[tid] = wim;
        s_cre[tid] = cbre; s_cim[tid] = cbim;
        // ladder: 6 squarings to w^64, then store w^{64*2^k}, k=0..3
        float pr = wre, pi = wim;
        #pragma unroll
        for (int k = 0; k < 6; k++) {
            float nr = fmaf(pr, pr, -pi * pi);
            float ni = 2.0f * pr * pi;
            pr = nr; pi = ni;
        }
        #pragma unroll
        for (int k = 0; k < 4; k++) {
            s_pre[k][tid] = pr;
            s_pim[k][tid] = pi;
            float nr = fmaf(pr, pr, -pi * pi);
            float ni = 2.0f * pr * pi;
            pr = nr; pi = ni;
        }
    }
    __syncthreads();

    // ---- main: packed second-order real recurrence ----
    const int g  = tid & (NG - 1);   // state group (lane & 7)
    const int t  = tid >> 3;         // l-chunk (0..15)

    float x0[NG], x1[NG], av[NG], bv[NG];
    #pragma unroll
    for (int j = 0; j < NG; j++) {
        const int n = g * NG + j;
        const float wre = s_wre[n], wim = s_wim[n];
        const float cbre = s_cre[n], cbim = s_cim[n];
        av[j] = 2.0f * wre;
        bv[j] = -fmaf(wre, wre, wim * wim);
        // z = w^{64t} via binary ladder over 4 bits of t
        float zr = 1.0f, zi = 0.0f;
        #pragma unroll
        for (int k = 0; k < 4; k++) {
            if (t & (1 << k)) {
                float pr = s_pre[k][n], pi = s_pim[k][n];
                float nr = fmaf(zr, pr, -zi * pi);
                float ni = fmaf(zr, pi,  zi * pr);
                zr = nr; zi = ni;
            }
        }
        x0[j] = fmaf(cbre, zr, -cbim * zi);          // Re(cb * w^l0)
        float z1r = fmaf(zr, wre, -zi * wim);
        float z1i = fmaf(zr, wim,  zi * wre);
        x1[j] = fmaf(cbre, z1r, -cbim * z1i);        // Re(cb * w^(l0+1))
    }

    u64 P[NP], Q[NP], A2[NP], BN[NP];
    #pragma unroll
    for (int k = 0; k < NP; k++) {
        P[k]  = pack2(x0[2*k], x0[2*k+1]);
        Q[k]  = pack2(x1[2*k], x1[2*k+1]);
        A2[k] = pack2(av[2*k], av[2*k+1]);
        BN[k] = pack2(bv[2*k], bv[2*k+1]);
    }

    // quarter q = g>>1; lanes with even g store pair-sums
    const int qd = g >> 1;
    const bool storer = (g & 1) == 0;
    float* pbase = &s_part[qd * QSTRIDE + t * TROW];

    #pragma unroll
    for (int ib = 0; ib < CHUNK; ib += 4) {
        float p[4];
        #pragma unroll
        for (int ii = 0; ii < 4; ii++) {
            // partial sum over this thread's 8 states at l = t*64 + ib + ii
            u64 s01 = add2(P[0], P[1]);
            u64 s23 = add2(P[2], P[3]);
            u64 sp  = add2(s01, s23);
            float lo, hi;
            unpack2(sp, lo, hi);
            p[ii] = lo + hi;
            // advance: x_{l+2} = a*x_{l+1} + bn*x_l
            #pragma unroll
            for (int k = 0; k < NP; k++) {
                u64 tt = mul2(BN[k], P[k]);
                u64 r2 = fma2(A2[k], Q[k], tt);
                P[k] = Q[k];
                Q[k] = r2;
            }
        }
        // 4 independent shfl chains — latencies overlap
        #pragma unroll
        for (int ii = 0; ii < 4; ii++)
            p[ii] += __shfl_xor_sync(0xffffffffu, p[ii], 1);
        if (storer) {
            float4 v4 = make_float4(p[0], p[1], p[2], p[3]);
            *reinterpret_cast<float4*>(&pbase[ib]) = v4;
        }
    }
    __syncthreads();

    // ---- epilogue: add the 4 quarters, write gmem coalesced ----
    const float Dh = Dm[h];
    float* outh = out + (size_t)h * LL;
    #pragma unroll
    for (int k = 0; k < 8; k++) {
        const int l  = k * THREADS + tid;
        const int tt = l >> 6;            // chunk
        const int ii = l & 63;            // offset in chunk
        const int a  = tt * TROW + ii;
        float v = (s_part[a] + s_part[a + QSTRIDE])
                + (s_part[a + 2*QSTRIDE] + s_part[a + 3*QSTRIDE]);
        if (l == 0) v += Dh;
        outh[l] = v;
    }
}

extern "C" void kernel_launch(void* const* d_in, const int* in_sizes, int n_in,
                              void* d_out, int out_size) {
    const float* log_dt = (const float*)d_in[0];
    const float* Lre    = (const float*)d_in[1];
    const float* Lim    = (const float*)d_in[2];
    const float* Bm     = (const float*)d_in[3];
    const float* Cre    = (const float*)d_in[4];
    const float* Cim    = (const float*)d_in[5];
    const float* Dm     = (const float*)d_in[6];
    float* out = (float*)d_out;
    ssk_diag_kernel<<<HH, THREADS>>>(log_dt, Lre, Lim, Bm, Cre, Cim, Dm, out);
}

// round 9
// speedup vs baseline: 1.7121x; 1.0195x over previous
#include <cuda_runtime.h>
#include <cuda_bf16.h>
#include <math.h>

#define HH 1024
#define NN 64
#define LL 1024
#define NG 8            // states per thread
#define LT 16           // l-chunks
#define CHUNK (LL/LT)   // 64 l per thread
#define THREADS (LT*NG) // 128
#define NP (NG/2)
#define TROW 68         // per-chunk row stride (floats), 16B-aligned
#define QSTRIDE (LT*TROW + 8)  // 1096: quarter stride, bank offset 8

typedef unsigned long long u64;

__device__ __forceinline__ u64 pack2(float lo, float hi) {
    u64 r; asm("mov.b64 %0, {%1, %2};" : "=l"(r) : "f"(lo), "f"(hi)); return r;
}
__device__ __forceinline__ void unpack2(u64 v, float& lo, float& hi) {
    asm("mov.b64 {%0, %1}, %2;" : "=f"(lo), "=f"(hi) : "l"(v));
}
__device__ __forceinline__ u64 mul2(u64 a, u64 b) {
    u64 r; asm("mul.rn.f32x2 %0, %1, %2;" : "=l"(r) : "l"(a), "l"(b)); return r;
}
__device__ __forceinline__ u64 fma2(u64 a, u64 b, u64 c) {
    u64 r; asm("fma.rn.f32x2 %0, %1, %2, %3;" : "=l"(r) : "l"(a), "l"(b), "l"(c)); return r;
}
__device__ __forceinline__ u64 add2(u64 a, u64 b) {
    u64 r; asm("add.rn.f32x2 %0, %1, %2;" : "=l"(r) : "l"(a), "l"(b)); return r;
}

__global__ __launch_bounds__(THREADS)
void ssk_diag_kernel(const float* __restrict__ log_dt,
                     const float* __restrict__ Lre,
                     const float* __restrict__ Lim,
                     const float* __restrict__ Bm,
                     const float* __restrict__ Cre,
                     const float* __restrict__ Cim,
                     const float* __restrict__ Dm,
                     float* __restrict__ out) {
    const int h = blockIdx.x;
    __shared__ float s_wre[NN], s_wim[NN];       // w = exp(dtA)
    __shared__ float s_cre[NN], s_cim[NN];       // 2*C*B_bar
    __shared__ float s_pre[4][NN], s_pim[4][NN]; // w^{64*2^k}, k=0..3
    __shared__ float s_part[4 * QSTRIDE];        // 4 quarter-sums per l

    const int tid = threadIdx.x;

    // ---- setup: per-state parameters (64 threads) ----
    if (tid < NN) {
        const int idx = h * NN + tid;
        float dt  = expf(log_dt[h]);
        float lre = Lre[idx];
        float lim = Lim[idx];
        float are = dt * lre;
        float aim = dt * lim;
        float er  = expf(are);
        float s, c;
        sincosf(aim, &s, &c);            // sin first, cos second
        float wre = er * c;
        float wim = er * s;
        // expm1(dtA): Re = expm1(are)*cos(aim) - 2*sin^2(aim/2), Im = e^are*sin(aim)
        float em   = expm1f(are);
        float sh   = sinf(0.5f * aim);
        float emre = fmaf(em, c, -2.0f * sh * sh);
        float emim = er * s;
        // B_bar = expm1(dtA)/Lambda * B
        float inv  = 1.0f / fmaf(lre, lre, lim * lim);
        float bre  = (emre * lre + emim * lim) * inv;
        float bim  = (emim * lre - emre * lim) * inv;
        float b    = Bm[idx];
        bre *= b;  bim *= b;
        // CB = C * B_bar, fold factor 2
        float cr = Cre[idx], ci = Cim[idx];
        float cbre = 2.0f * (cr * bre - ci * bim);
        float cbim = 2.0f * (cr * bim + ci * bre);
        s_wre[tid] = wre;  s_wim[tid] = wim;
        s_cre[tid] = cbre; s_cim[tid] = cbim;
        // ladder: 6 squarings to w^64, then store w^{64*2^k}, k=0..3
        float pr = wre, pi = wim;
        #pragma unroll
        for (int k = 0; k < 6; k++) {
            float nr = fmaf(pr, pr, -pi * pi);
            float ni = 2.0f * pr * pi;
            pr = nr; pi = ni;
        }
        #pragma unroll
        for (int k = 0; k < 4; k++) {
            s_pre[k][tid] = pr;
            s_pim[k][tid] = pi;
            float nr = fmaf(pr, pr, -pi * pi);
            float ni = 2.0f * pr * pi;
            pr = nr; pi = ni;
        }
    }
    __syncthreads();

    // ---- main: packed second-order real recurrence ----
    const int g  = tid & (NG - 1);   // state group (lane & 7)
    const int t  = tid >> 3;         // l-chunk (0..15)

    float x0[NG], x1[NG], av[NG], bv[NG];
    #pragma unroll
    for (int j = 0; j < NG; j++) {
        const int n = g * NG + j;
        const float wre = s_wre[n], wim = s_wim[n];
        const float cbre = s_cre[n], cbim = s_cim[n];
        av[j] = 2.0f * wre;
        bv[j] = -fmaf(wre, wre, wim * wim);
        // z = w^{64t} via binary ladder over 4 bits of t
        float zr = 1.0f, zi = 0.0f;
        #pragma unroll
        for (int k = 0; k < 4; k++) {
            if (t & (1 << k)) {
                float pr = s_pre[k][n], pi = s_pim[k][n];
                float nr = fmaf(zr, pr, -zi * pi);
                float ni = fmaf(zr, pi,  zi * pr);
                zr = nr; zi = ni;
            }
        }
        x0[j] = fmaf(cbre, zr, -cbim * zi);          // Re(cb * w^l0)
        float z1r = fmaf(zr, wre, -zi * wim);
        float z1i = fmaf(zr, wim,  zi * wre);
        x1[j] = fmaf(cbre, z1r, -cbim * z1i);        // Re(cb * w^(l0+1))
    }

    u64 P[NP], Q[NP], A2[NP], BN[NP];
    #pragma unroll
    for (int k = 0; k < NP; k++) {
        P[k]  = pack2(x0[2*k], x0[2*k+1]);
        Q[k]  = pack2(x1[2*k], x1[2*k+1]);
        A2[k] = pack2(av[2*k], av[2*k+1]);
        BN[k] = pack2(bv[2*k], bv[2*k+1]);
    }

    // quarter q = g>>1; lanes with even g store pair-sums
    const int qd = g >> 1;
    const bool storer = (g & 1) == 0;
    float* pbase = &s_part[qd * QSTRIDE + t * TROW];

    #pragma unroll
    for (int ib = 0; ib < CHUNK; ib += 4) {
        float p[4];
        #pragma unroll
        for (int ii = 0; ii < 4; ii++) {
            // partial sum over this thread's 8 states at l = t*64 + ib + ii
            u64 s01 = add2(P[0], P[1]);
            u64 s23 = add2(P[2], P[3]);
            u64 sp  = add2(s01, s23);
            float lo, hi;
            unpack2(sp, lo, hi);
            p[ii] = lo + hi;
            // advance: x_{l+2} = a*x_{l+1} + bn*x_l
            #pragma unroll
            for (int k = 0; k < NP; k++) {
                u64 tt = mul2(BN[k], P[k]);
                u64 r2 = fma2(A2[k], Q[k], tt);
                P[k] = Q[k];
                Q[k] = r2;
            }
        }
        // 4 independent shfl chains — latencies overlap
        #pragma unroll
        for (int ii = 0; ii < 4; ii++)
            p[ii] += __shfl_xor_sync(0xffffffffu, p[ii], 1);
        if (storer) {
            float4 v4 = make_float4(p[0], p[1], p[2], p[3]);
            *reinterpret_cast<float4*>(&pbase[ib]) = v4;
        }
    }
    __syncthreads();

    // ---- epilogue: add the 4 quarters, write gmem coalesced ----
    const float Dh = Dm[h];
    float* outh = out + (size_t)h * LL;
    #pragma unroll
    for (int k = 0; k < 8; k++) {
        const int l  = k * THREADS + tid;
        const int tt = l >> 6;            // chunk
        const int ii = l & 63;            // offset in chunk
        const int a  = tt * TROW + ii;
        float v = (s_part[a] + s_part[a + QSTRIDE])
                + (s_part[a + 2*QSTRIDE] + s_part[a + 3*QSTRIDE]);
        if (l == 0) v += Dh;
        outh[l] = v;
    }
}

extern "C" void kernel_launch(void* const* d_in, const int* in_sizes, int n_in,
                              void* d_out, int out_size) {
    const float* log_dt = (const float*)d_in[0];
    const float* Lre    = (const float*)d_in[1];
    const float* Lim    = (const float*)d_in[2];
    const float* Bm     = (const float*)d_in[3];
    const float* Cre    = (const float*)d_in[4];
    const float* Cim    = (const float*)d_in[5];
    const float* Dm     = (const float*)d_in[6];
    float* out = (float*)d_out;
    ssk_diag_kernel<<<HH, THREADS>>>(log_dt, Lre, Lim, Bm, Cre, Cim, Dm, out);
}